// round 10
// baseline (speedup 1.0000x reference)
#include <cuda_runtime.h>
#include <cstdint>

#define E_N 100000
#define T_N 400000

// Scratch (device globals — no runtime alloc).
__device__ float    g_seg[(long long)E_N * 128];
__device__ float    g_cnt[E_N];
__device__ uint32_t g_fe[(long long)E_N * 128];   // f_edge pre-rounded to tf32
__device__ uint32_t g_Wc[384 * 128];              // W pre-rounded to tf32

// ---------------------------------------------------------------------------
// helpers
// ---------------------------------------------------------------------------
__device__ __forceinline__ uint32_t f2tf(float f) {
    uint32_t o;
    asm("cvt.rna.tf32.f32 %0, %1;" : "=r"(o) : "f"(f));
    return o;
}

__device__ __forceinline__ void mma8(float c[4], const uint32_t a[4],
                                     uint32_t b0, uint32_t b1) {
    asm volatile(
        "mma.sync.aligned.m16n8k8.row.col.f32.tf32.tf32.f32 "
        "{%0,%1,%2,%3}, {%4,%5,%6,%7}, {%8,%9}, {%0,%1,%2,%3};\n"
        : "+f"(c[0]), "+f"(c[1]), "+f"(c[2]), "+f"(c[3])
        : "r"(a[0]), "r"(a[1]), "r"(a[2]), "r"(a[3]), "r"(b0), "r"(b1));
}

__device__ __forceinline__ float gelu_exact(float x) {
    return 0.5f * x * (1.0f + erff(x * 0.70710678118654752f));
}

__device__ __forceinline__ void cpa16(uint32_t dst_smem, const void* src) {
    asm volatile("cp.async.cg.shared.global [%0], [%1], 16;"
                 :: "r"(dst_smem), "l"(src));
}

// ---------------------------------------------------------------------------
// kernel 0: fused init — tf32-convert f_edge & W, zero g_seg / g_cnt
// ---------------------------------------------------------------------------
__global__ void init_kernel(const float* __restrict__ fe,
                            const float* __restrict__ W) {
    int i = blockIdx.x * 256 + threadIdx.x;          // 12500*256 = 3.2M float4s
    float4 v = ((const float4*)fe)[i];
    uint4 o;
    o.x = f2tf(v.x); o.y = f2tf(v.y); o.z = f2tf(v.z); o.w = f2tf(v.w);
    ((uint4*)g_fe)[i] = o;
    ((float4*)g_seg)[i] = make_float4(0.f, 0.f, 0.f, 0.f);
    if (i < 12288) {                                  // 384*128/4
        float4 w = ((const float4*)W)[i];
        uint4 ow;
        ow.x = f2tf(w.x); ow.y = f2tf(w.y); ow.z = f2tf(w.z); ow.w = f2tf(w.w);
        ((uint4*)g_Wc)[i] = ow;
    }
    if (i < E_N) g_cnt[i] = 0.0f;
}

// ---------------------------------------------------------------------------
// kernel 1: gather + tf32 GEMM (3-stage cp.async) + GELU + bulk-reduce scatter
//   BM=128, BN=128, BK=16, 24 chunks, 3 smem stages, 1 barrier/chunk.
//   Epilogue: stage 128x128 tile in smem (stride 136), then per-row
//   cp.reduce.async.bulk f32-add into g_seg.
// ---------------------------------------------------------------------------
#define NSTAGE   3
#define A_STRIDE 20          // floats; (20*gid + t4) mod 32 all-distinct
#define B_STRIDE 136         // floats; (8*t4 + gid) mod 32 all-distinct
#define STAGE_U32 (128 * A_STRIDE + 16 * B_STRIDE)   // 2560 + 2176 = 4736
#define EPI_STRIDE 136       // floats; row = 544B (16B multiple)
#define DYN_SMEM  (128 * EPI_STRIDE * 4)             // 69632 >= 3*18944

__global__ __launch_bounds__(256, 2)
void tri_gemm_kernel(const float* __restrict__ bias,
                     const int* __restrict__ tri) {
    extern __shared__ uint32_t dyn[];
    __shared__ int   sIdx[384];          // [128][3]
    __shared__ float sBias[128];

    const int tid = threadIdx.x;
    const int t0  = blockIdx.x * 128;    // T = 3125 * 128

    for (int i = tid; i < 384; i += 256) sIdx[i] = tri[(long long)t0 * 3 + i];
    if (tid < 128) sBias[tid] = bias[tid];
    __syncthreads();

    if (tid < 128) atomicAdd(&g_cnt[sIdx[tid * 3 + 2]], 1.0f);

    const int lane  = tid & 31;
    const int warp  = tid >> 5;
    const int warpM = warp & 3;
    const int warpN = warp >> 2;
    const int gid   = lane >> 2;
    const int t4    = lane & 3;

    // cp.async mapping: 2 x 16B for A, 2 x 16B for B per chunk per thread
    const int ra0 = tid >> 2;            // A row (0..63), +64 for second
    const int qa  = (tid & 3) * 4;       // A k-offset (floats)
    const int rb0 = tid >> 5;            // B row (0..7), +8 for second
    const int qb  = (tid & 31) * 4;      // B n-offset (floats)

    const uint32_t dynb = (uint32_t)__cvta_generic_to_shared(dyn);

    float acc[2][8][4];
#pragma unroll
    for (int a = 0; a < 2; ++a)
#pragma unroll
        for (int b = 0; b < 8; ++b)
#pragma unroll
            for (int c = 0; c < 4; ++c) acc[a][b][c] = 0.0f;

    auto load_chunk = [&](int ch) {
        const int st   = ch % NSTAGE;
        const int j    = ch >> 3;            // edge slot 0..2
        const int off  = (ch & 7) * 16;      // k-offset within edge row
        const uint32_t aB = dynb + (st * STAGE_U32) * 4;
        const uint32_t bB = aB + 128 * A_STRIDE * 4;
        cpa16(aB + (ra0 * A_STRIDE + qa) * 4,
              g_fe + (long long)sIdx[ra0 * 3 + j] * 128 + off + qa);
        cpa16(aB + ((ra0 + 64) * A_STRIDE + qa) * 4,
              g_fe + (long long)sIdx[(ra0 + 64) * 3 + j] * 128 + off + qa);
        cpa16(bB + (rb0 * B_STRIDE + qb) * 4, g_Wc + (ch * 16 + rb0) * 128 + qb);
        cpa16(bB + ((rb0 + 8) * B_STRIDE + qb) * 4,
              g_Wc + (ch * 16 + rb0 + 8) * 128 + qb);
        asm volatile("cp.async.commit_group;" ::: "memory");
    };

    load_chunk(0);
    load_chunk(1);

    for (int ch = 0; ch < 24; ++ch) {
        asm volatile("cp.async.wait_group 1;" ::: "memory");
        __syncthreads();
        if (ch + 2 < 24) load_chunk(ch + 2);

        const int st = ch % NSTAGE;
        const uint32_t* A = dyn + st * STAGE_U32;
        const uint32_t* B = A + 128 * A_STRIDE;
#pragma unroll
        for (int kk = 0; kk < 2; ++kk) {
            const int k0 = kk * 8;
            uint32_t afr[2][4];
#pragma unroll
            for (int mt = 0; mt < 2; ++mt) {
                int rb = warpM * 32 + mt * 16 + gid;
                afr[mt][0] = A[rb * A_STRIDE + k0 + t4];
                afr[mt][1] = A[(rb + 8) * A_STRIDE + k0 + t4];
                afr[mt][2] = A[rb * A_STRIDE + k0 + t4 + 4];
                afr[mt][3] = A[(rb + 8) * A_STRIDE + k0 + t4 + 4];
            }
#pragma unroll
            for (int nt = 0; nt < 8; ++nt) {
                int nb = warpN * 64 + nt * 8 + gid;
                uint32_t b0 = B[(k0 + t4) * B_STRIDE + nb];
                uint32_t b1 = B[(k0 + t4 + 4) * B_STRIDE + nb];
                mma8(acc[0][nt], afr[0], b0, b1);
                mma8(acc[1][nt], afr[1], b0, b1);
            }
        }
    }

    // ---- Epilogue: bias + exact GELU -> smem tile -> per-row bulk reduce ----
    __syncthreads();     // all compute done; safe to overwrite stage buffers
    float2* epi = (float2*)dyn;
#pragma unroll
    for (int mt = 0; mt < 2; ++mt) {
        int r0 = warpM * 32 + mt * 16 + gid;
#pragma unroll
        for (int nt = 0; nt < 8; ++nt) {
            int c0 = warpN * 64 + nt * 8 + t4 * 2;
            float bv0 = sBias[c0], bv1 = sBias[c0 + 1];
            float2 v0, v1;
            v0.x = gelu_exact(acc[mt][nt][0] + bv0);
            v0.y = gelu_exact(acc[mt][nt][1] + bv1);
            v1.x = gelu_exact(acc[mt][nt][2] + bv0);
            v1.y = gelu_exact(acc[mt][nt][3] + bv1);
            epi[(r0 * EPI_STRIDE + c0) >> 1] = v0;
            epi[((r0 + 8) * EPI_STRIDE + c0) >> 1] = v1;
        }
    }
    __syncthreads();
    asm volatile("fence.proxy.async.shared::cta;" ::: "memory");

    if (tid < 128) {
        float* gdst = g_seg + (long long)sIdx[tid * 3 + 2] * 128;
        uint32_t src = dynb + tid * (EPI_STRIDE * 4);
        asm volatile(
            "cp.reduce.async.bulk.global.shared::cta.bulk_group.add.f32 "
            "[%0], [%1], 512;"
            :: "l"(gdst), "r"(src) : "memory");
        asm volatile("cp.async.bulk.commit_group;" ::: "memory");
        asm volatile("cp.async.bulk.wait_group 0;" ::: "memory");
    }
}

// ---------------------------------------------------------------------------
// kernel 2: segment mean + layernorm. One warp per edge.
// ---------------------------------------------------------------------------
__global__ __launch_bounds__(256)
void ln_kernel(const float* __restrict__ gamma,
               const float* __restrict__ beta,
               float* __restrict__ out) {
    const int warp = threadIdx.x >> 5;
    const int lane = threadIdx.x & 31;
    const int e = blockIdx.x * 8 + warp;
    if (e >= E_N) return;

    const float inv = 1.0f / fmaxf(g_cnt[e], 1.0f);
    const long long base = (long long)e * 128;

    float m[4];
    float s = 0.0f;
#pragma unroll
    for (int i = 0; i < 4; ++i) {
        m[i] = g_seg[base + lane + 32 * i] * inv;
        s += m[i];
    }
#pragma unroll
    for (int o = 16; o; o >>= 1) s += __shfl_xor_sync(0xffffffffu, s, o);
    const float mu = s * (1.0f / 128.0f);

    float v = 0.0f;
#pragma unroll
    for (int i = 0; i < 4; ++i) {
        float d = m[i] - mu;
        v += d * d;
    }
#pragma unroll
    for (int o = 16; o; o >>= 1) v += __shfl_xor_sync(0xffffffffu, v, o);
    const float rstd = rsqrtf(v * (1.0f / 128.0f) + 1e-5f);

#pragma unroll
    for (int i = 0; i < 4; ++i) {
        int c = lane + 32 * i;
        out[base + c] = (m[i] - mu) * rstd * gamma[c] + beta[c];
    }
}

// ---------------------------------------------------------------------------
extern "C" void kernel_launch(void* const* d_in, const int* in_sizes, int n_in,
                              void* d_out, int out_size) {
    const float* f_edge = nullptr;
    const float* W      = nullptr;
    const int*   tri    = nullptr;
    const float* vec128[3] = {nullptr, nullptr, nullptr};
    int nv = 0;
    for (int i = 0; i < n_in; ++i) {
        long long sz = in_sizes[i];
        if (sz == (long long)E_N * 128)  f_edge = (const float*)d_in[i];
        else if (sz == 3LL * 128 * 128)  W      = (const float*)d_in[i];
        else if (sz == 3LL * T_N)        tri    = (const int*)d_in[i];
        else if (sz == 128 && nv < 3)    vec128[nv++] = (const float*)d_in[i];
    }
    const float* b     = vec128[0];
    const float* gamma = vec128[1];
    const float* beta  = vec128[2];
    float* out = (float*)d_out;

    cudaFuncSetAttribute(tri_gemm_kernel,
                         cudaFuncAttributeMaxDynamicSharedMemorySize, DYN_SMEM);

    init_kernel<<<12500, 256>>>(f_edge, W);
    tri_gemm_kernel<<<T_N / 128, 256, DYN_SMEM>>>(b, tri);
    ln_kernel<<<E_N / 8, 256>>>(gamma, beta, out);
}

// round 11
// speedup vs baseline: 1.0057x; 1.0057x over previous
#include <cuda_runtime.h>
#include <cstdint>

#define E_N 100000
#define T_N 400000

// Scratch (device globals — no runtime alloc).
__device__ float    g_seg[(long long)E_N * 128];
__device__ float    g_cnt[E_N];
__device__ uint32_t g_fe[(long long)E_N * 128];   // f_edge pre-rounded to tf32
__device__ uint32_t g_Wc[384 * 128];              // W pre-rounded to tf32

// ---------------------------------------------------------------------------
// helpers
// ---------------------------------------------------------------------------
__device__ __forceinline__ uint32_t f2tf(float f) {
    uint32_t o;
    asm("cvt.rna.tf32.f32 %0, %1;" : "=r"(o) : "f"(f));
    return o;
}

__device__ __forceinline__ void mma8(float c[4], const uint32_t a[4],
                                     uint32_t b0, uint32_t b1) {
    asm volatile(
        "mma.sync.aligned.m16n8k8.row.col.f32.tf32.tf32.f32 "
        "{%0,%1,%2,%3}, {%4,%5,%6,%7}, {%8,%9}, {%0,%1,%2,%3};\n"
        : "+f"(c[0]), "+f"(c[1]), "+f"(c[2]), "+f"(c[3])
        : "r"(a[0]), "r"(a[1]), "r"(a[2]), "r"(a[3]), "r"(b0), "r"(b1));
}

__device__ __forceinline__ void red2(float* p, float x, float y) {
    asm volatile("red.global.add.v2.f32 [%0], {%1,%2};"
                 :: "l"(p), "f"(x), "f"(y) : "memory");
}

__device__ __forceinline__ float gelu_exact(float x) {
    return 0.5f * x * (1.0f + erff(x * 0.70710678118654752f));
}

__device__ __forceinline__ void cpa16(uint32_t dst_smem, const void* src) {
    asm volatile("cp.async.cg.shared.global [%0], [%1], 16;"
                 :: "r"(dst_smem), "l"(src));
}

// ---------------------------------------------------------------------------
// kernel 0: fused init — tf32-convert f_edge & W, zero g_seg / g_cnt
// ---------------------------------------------------------------------------
__global__ void init_kernel(const float* __restrict__ fe,
                            const float* __restrict__ W) {
    int i = blockIdx.x * 256 + threadIdx.x;          // 12500*256 = 3.2M float4s
    float4 v = ((const float4*)fe)[i];
    uint4 o;
    o.x = f2tf(v.x); o.y = f2tf(v.y); o.z = f2tf(v.z); o.w = f2tf(v.w);
    ((uint4*)g_fe)[i] = o;
    ((float4*)g_seg)[i] = make_float4(0.f, 0.f, 0.f, 0.f);
    if (i < 12288) {                                  // 384*128/4
        float4 w = ((const float4*)W)[i];
        uint4 ow;
        ow.x = f2tf(w.x); ow.y = f2tf(w.y); ow.z = f2tf(w.z); ow.w = f2tf(w.w);
        ((uint4*)g_Wc)[i] = ow;
    }
    if (i < E_N) g_cnt[i] = 0.0f;
}

// ---------------------------------------------------------------------------
// kernel 1: gather + tf32 GEMM (3-stage cp.async, 1 barrier/chunk)
//           + exact GELU + fire-and-forget red.global.add.v2 scatter
//   BM=128, BN=128, BK=16, 24 chunks, 3 smem stages.
// ---------------------------------------------------------------------------
#define NSTAGE   3
#define A_STRIDE 20          // floats; (20*gid + t4) mod 32 all-distinct
#define B_STRIDE 136         // floats; (8*t4 + gid) mod 32 all-distinct
#define STAGE_U32 (128 * A_STRIDE + 16 * B_STRIDE)   // 2560 + 2176 = 4736
#define DYN_SMEM  (NSTAGE * STAGE_U32 * 4)           // 56832 B

__global__ __launch_bounds__(256, 2)
void tri_gemm_kernel(const float* __restrict__ bias,
                     const int* __restrict__ tri) {
    extern __shared__ uint32_t dyn[];
    __shared__ int   sIdx[384];          // [128][3]
    __shared__ float sBias[128];

    const int tid = threadIdx.x;
    const int t0  = blockIdx.x * 128;    // T = 3125 * 128

    for (int i = tid; i < 384; i += 256) sIdx[i] = tri[(long long)t0 * 3 + i];
    if (tid < 128) sBias[tid] = bias[tid];
    __syncthreads();

    if (tid < 128) atomicAdd(&g_cnt[sIdx[tid * 3 + 2]], 1.0f);

    const int lane  = tid & 31;
    const int warp  = tid >> 5;
    const int warpM = warp & 3;
    const int warpN = warp >> 2;
    const int gid   = lane >> 2;
    const int t4    = lane & 3;

    // cp.async mapping: 2 x 16B for A, 2 x 16B for B per chunk per thread
    const int ra0 = tid >> 2;            // A row (0..63), +64 for second
    const int qa  = (tid & 3) * 4;       // A k-offset (floats)
    const int rb0 = tid >> 5;            // B row (0..7), +8 for second
    const int qb  = (tid & 31) * 4;      // B n-offset (floats)

    const uint32_t dynb = (uint32_t)__cvta_generic_to_shared(dyn);

    float acc[2][8][4];
#pragma unroll
    for (int a = 0; a < 2; ++a)
#pragma unroll
        for (int b = 0; b < 8; ++b)
#pragma unroll
            for (int c = 0; c < 4; ++c) acc[a][b][c] = 0.0f;

    auto load_chunk = [&](int ch) {
        const int st   = ch % NSTAGE;
        const int j    = ch >> 3;            // edge slot 0..2
        const int off  = (ch & 7) * 16;      // k-offset within edge row
        const uint32_t aB = dynb + (st * STAGE_U32) * 4;
        const uint32_t bB = aB + 128 * A_STRIDE * 4;
        cpa16(aB + (ra0 * A_STRIDE + qa) * 4,
              g_fe + (long long)sIdx[ra0 * 3 + j] * 128 + off + qa);
        cpa16(aB + ((ra0 + 64) * A_STRIDE + qa) * 4,
              g_fe + (long long)sIdx[(ra0 + 64) * 3 + j] * 128 + off + qa);
        cpa16(bB + (rb0 * B_STRIDE + qb) * 4, g_Wc + (ch * 16 + rb0) * 128 + qb);
        cpa16(bB + ((rb0 + 8) * B_STRIDE + qb) * 4,
              g_Wc + (ch * 16 + rb0 + 8) * 128 + qb);
        asm volatile("cp.async.commit_group;" ::: "memory");
    };

    load_chunk(0);
    load_chunk(1);

    for (int ch = 0; ch < 24; ++ch) {
        asm volatile("cp.async.wait_group 1;" ::: "memory");
        __syncthreads();
        if (ch + 2 < 24) load_chunk(ch + 2);

        const int st = ch % NSTAGE;
        const uint32_t* A = dyn + st * STAGE_U32;
        const uint32_t* B = A + 128 * A_STRIDE;
#pragma unroll
        for (int kk = 0; kk < 2; ++kk) {
            const int k0 = kk * 8;
            uint32_t afr[2][4];
#pragma unroll
            for (int mt = 0; mt < 2; ++mt) {
                int rb = warpM * 32 + mt * 16 + gid;
                afr[mt][0] = A[rb * A_STRIDE + k0 + t4];
                afr[mt][1] = A[(rb + 8) * A_STRIDE + k0 + t4];
                afr[mt][2] = A[rb * A_STRIDE + k0 + t4 + 4];
                afr[mt][3] = A[(rb + 8) * A_STRIDE + k0 + t4 + 4];
            }
#pragma unroll
            for (int nt = 0; nt < 8; ++nt) {
                int nb = warpN * 64 + nt * 8 + gid;
                uint32_t b0 = B[(k0 + t4) * B_STRIDE + nb];
                uint32_t b1 = B[(k0 + t4 + 4) * B_STRIDE + nb];
                mma8(acc[0][nt], afr[0], b0, b1);
                mma8(acc[1][nt], afr[1], b0, b1);
            }
        }
    }

    // Epilogue: bias + exact GELU + fire-and-forget vectorized reduction
#pragma unroll
    for (int mt = 0; mt < 2; ++mt) {
        int r0 = warpM * 32 + mt * 16 + gid;
        int dst0 = sIdx[r0 * 3 + 2];
        int dst1 = sIdx[(r0 + 8) * 3 + 2];
        float* p0 = g_seg + (long long)dst0 * 128;
        float* p1 = g_seg + (long long)dst1 * 128;
#pragma unroll
        for (int nt = 0; nt < 8; ++nt) {
            int c0 = warpN * 64 + nt * 8 + t4 * 2;
            float bv0 = sBias[c0], bv1 = sBias[c0 + 1];
            float x0 = gelu_exact(acc[mt][nt][0] + bv0);
            float x1 = gelu_exact(acc[mt][nt][1] + bv1);
            float x2 = gelu_exact(acc[mt][nt][2] + bv0);
            float x3 = gelu_exact(acc[mt][nt][3] + bv1);
            red2(p0 + c0, x0, x1);
            red2(p1 + c0, x2, x3);
        }
    }
}

// ---------------------------------------------------------------------------
// kernel 2: segment mean + layernorm. One warp per edge.
// ---------------------------------------------------------------------------
__global__ __launch_bounds__(256)
void ln_kernel(const float* __restrict__ gamma,
               const float* __restrict__ beta,
               float* __restrict__ out) {
    const int warp = threadIdx.x >> 5;
    const int lane = threadIdx.x & 31;
    const int e = blockIdx.x * 8 + warp;
    if (e >= E_N) return;

    const float inv = 1.0f / fmaxf(g_cnt[e], 1.0f);
    const long long base = (long long)e * 128;

    float m[4];
    float s = 0.0f;
#pragma unroll
    for (int i = 0; i < 4; ++i) {
        m[i] = g_seg[base + lane + 32 * i] * inv;
        s += m[i];
    }
#pragma unroll
    for (int o = 16; o; o >>= 1) s += __shfl_xor_sync(0xffffffffu, s, o);
    const float mu = s * (1.0f / 128.0f);

    float v = 0.0f;
#pragma unroll
    for (int i = 0; i < 4; ++i) {
        float d = m[i] - mu;
        v += d * d;
    }
#pragma unroll
    for (int o = 16; o; o >>= 1) v += __shfl_xor_sync(0xffffffffu, v, o);
    const float rstd = rsqrtf(v * (1.0f / 128.0f) + 1e-5f);

#pragma unroll
    for (int i = 0; i < 4; ++i) {
        int c = lane + 32 * i;
        out[base + c] = (m[i] - mu) * rstd * gamma[c] + beta[c];
    }
}

// ---------------------------------------------------------------------------
extern "C" void kernel_launch(void* const* d_in, const int* in_sizes, int n_in,
                              void* d_out, int out_size) {
    const float* f_edge = nullptr;
    const float* W      = nullptr;
    const int*   tri    = nullptr;
    const float* vec128[3] = {nullptr, nullptr, nullptr};
    int nv = 0;
    for (int i = 0; i < n_in; ++i) {
        long long sz = in_sizes[i];
        if (sz == (long long)E_N * 128)  f_edge = (const float*)d_in[i];
        else if (sz == 3LL * 128 * 128)  W      = (const float*)d_in[i];
        else if (sz == 3LL * T_N)        tri    = (const int*)d_in[i];
        else if (sz == 128 && nv < 3)    vec128[nv++] = (const float*)d_in[i];
    }
    const float* b     = vec128[0];
    const float* gamma = vec128[1];
    const float* beta  = vec128[2];
    float* out = (float*)d_out;

    cudaFuncSetAttribute(tri_gemm_kernel,
                         cudaFuncAttributeMaxDynamicSharedMemorySize, DYN_SMEM);

    init_kernel<<<12500, 256>>>(f_edge, W);
    tri_gemm_kernel<<<T_N / 128, 256, DYN_SMEM>>>(b, tri);
    ln_kernel<<<E_N / 8, 256>>>(gamma, beta, out);
}

// round 14
// speedup vs baseline: 1.3880x; 1.3800x over previous
#include <cuda_runtime.h>
#include <cuda_fp16.h>
#include <cstdint>

#define E_N 100000
#define T_N 400000

// Scratch (device globals — no runtime alloc).
__device__ float    g_seg[(long long)E_N * 128];
__device__ float    g_cnt[E_N];
__device__ uint32_t g_fh[(long long)E_N * 64];    // f_edge fp16, [e][k] packed half2
__device__ uint32_t g_Wh[128 * 192];              // W fp16 TRANSPOSED: [n][k] half2

// ---------------------------------------------------------------------------
// helpers
// ---------------------------------------------------------------------------
__device__ __forceinline__ void mma16(float c[4], const uint32_t a[4],
                                      uint32_t b0, uint32_t b1) {
    asm volatile(
        "mma.sync.aligned.m16n8k16.row.col.f32.f16.f16.f32 "
        "{%0,%1,%2,%3}, {%4,%5,%6,%7}, {%8,%9}, {%0,%1,%2,%3};\n"
        : "+f"(c[0]), "+f"(c[1]), "+f"(c[2]), "+f"(c[3])
        : "r"(a[0]), "r"(a[1]), "r"(a[2]), "r"(a[3]), "r"(b0), "r"(b1));
}

__device__ __forceinline__ void red2(float* p, float x, float y) {
    asm volatile("red.global.add.v2.f32 [%0], {%1,%2};"
                 :: "l"(p), "f"(x), "f"(y) : "memory");
}

__device__ __forceinline__ float gelu_exact(float x) {
    return 0.5f * x * (1.0f + erff(x * 0.70710678118654752f));
}

__device__ __forceinline__ void cpa16(uint32_t dst_smem, const void* src) {
    asm volatile("cp.async.cg.shared.global [%0], [%1], 16;"
                 :: "r"(dst_smem), "l"(src));
}

__device__ __forceinline__ uint32_t pack2h(float lo, float hi) {
    __half2 h = __floats2half2_rn(lo, hi);
    return *reinterpret_cast<uint32_t*>(&h);
}

// ---------------------------------------------------------------------------
// kernel 0: init — fp16-convert f_edge, fp16-transpose W, zero g_seg / g_cnt
// grid 12500 x 256
// ---------------------------------------------------------------------------
__global__ void init_kernel(const float* __restrict__ fe,
                            const float* __restrict__ W) {
    int i = blockIdx.x * 256 + threadIdx.x;          // 0 .. 3.2M-1
    float4 v = ((const float4*)fe)[i];
    g_fh[2 * i]     = pack2h(v.x, v.y);
    g_fh[2 * i + 1] = pack2h(v.z, v.w);
    ((float4*)g_seg)[i] = make_float4(0.f, 0.f, 0.f, 0.f);
    if (i < 24576) {                                  // 128 n x 192 k-pairs
        int n = i / 192, kk = i % 192;
        g_Wh[n * 192 + kk] = pack2h(W[(2 * kk) * 128 + n],
                                    W[(2 * kk + 1) * 128 + n]);
    }
    if (i < E_N) g_cnt[i] = 0.0f;
}

// ---------------------------------------------------------------------------
// kernel 1: gather + fp16 GEMM (3-stage cp.async) + exact GELU + REDG scatter
//   BM=128, BN=128, BK=32, 12 chunks, 3 smem stages, 1 barrier/chunk.
//   A smem: [m][k] fp16, row stride 20 u32 (16 data + 4 pad)
//   B smem: [n][k] fp16, row stride 20 u32
// ---------------------------------------------------------------------------
#define NSTAGE   3
#define RS       20                          // u32 row stride (A and B)
#define STAGE_U32 (128 * RS * 2)             // A + B = 5120 u32
#define DYN_SMEM  (NSTAGE * STAGE_U32 * 4)   // 61440 B

__global__ __launch_bounds__(256, 2)
void tri_gemm_kernel(const float* __restrict__ bias,
                     const int* __restrict__ tri) {
    extern __shared__ uint32_t dyn[];
    __shared__ int   sIdx[384];              // [128][3]
    __shared__ float sBias[128];

    const int tid = threadIdx.x;
    const int t0  = blockIdx.x * 128;        // T = 3125 * 128

    for (int i = tid; i < 384; i += 256) sIdx[i] = tri[(long long)t0 * 3 + i];
    if (tid < 128) sBias[tid] = bias[tid];
    __syncthreads();

    if (tid < 128) atomicAdd(&g_cnt[sIdx[tid * 3 + 2]], 1.0f);

    const int lane  = tid & 31;
    const int warp  = tid >> 5;
    const int warpM = warp & 3;
    const int warpN = warp >> 2;
    const int gid   = lane >> 2;
    const int t4    = lane & 3;

    // cp.async mapping: A and B each 128 rows x 64 B -> 512 x 16B -> 2/thread
    // fid = tid + s*256 : row = fid>>2 (0..127), part = fid&3 (x16B)
    const uint32_t dynb = (uint32_t)__cvta_generic_to_shared(dyn);

    float acc[2][8][4];
#pragma unroll
    for (int a = 0; a < 2; ++a)
#pragma unroll
        for (int b = 0; b < 8; ++b)
#pragma unroll
            for (int c = 0; c < 4; ++c) acc[a][b][c] = 0.0f;

    auto load_chunk = [&](int ch) {
        const int st  = ch % NSTAGE;
        const int j   = ch >> 2;             // edge slot 0..2 (4 chunks each)
        const int ko  = (ch & 3) * 16;       // u32 offset within edge row (64 u32)
        const uint32_t aB = dynb + (st * STAGE_U32) * 4;
        const uint32_t bB = aB + 128 * RS * 4;
#pragma unroll
        for (int s = 0; s < 2; ++s) {
            int fid = tid + s * 256;
            int r = fid >> 2, part = fid & 3;
            cpa16(aB + (r * RS + part * 4) * 4,
                  g_fh + (long long)sIdx[r * 3 + j] * 64 + ko + part * 4);
            cpa16(bB + (r * RS + part * 4) * 4,
                  g_Wh + r * 192 + ch * 16 + part * 4);
        }
        asm volatile("cp.async.commit_group;" ::: "memory");
    };

    load_chunk(0);
    load_chunk(1);

    for (int ch = 0; ch < 12; ++ch) {
        asm volatile("cp.async.wait_group 1;" ::: "memory");
        __syncthreads();
        if (ch + 2 < 12) load_chunk(ch + 2);

        const int st = ch % NSTAGE;
        const uint32_t* A = dyn + st * STAGE_U32;
        const uint32_t* B = A + 128 * RS;
#pragma unroll
        for (int kk = 0; kk < 2; ++kk) {
            const int k0 = kk * 8;           // u32 offset of this k16 block
            uint32_t afr[2][4];
#pragma unroll
            for (int mt = 0; mt < 2; ++mt) {
                int rb = warpM * 32 + mt * 16 + gid;
                afr[mt][0] = A[rb * RS + k0 + t4];
                afr[mt][1] = A[(rb + 8) * RS + k0 + t4];
                afr[mt][2] = A[rb * RS + k0 + t4 + 4];
                afr[mt][3] = A[(rb + 8) * RS + k0 + t4 + 4];
            }
#pragma unroll
            for (int nt = 0; nt < 8; ++nt) {
                int nb = warpN * 64 + nt * 8 + gid;
                uint32_t b0 = B[nb * RS + k0 + t4];
                uint32_t b1 = B[nb * RS + k0 + t4 + 4];
                mma16(acc[0][nt], afr[0], b0, b1);
                mma16(acc[1][nt], afr[1], b0, b1);
            }
        }
    }

    // Epilogue: bias + exact GELU + fire-and-forget vectorized reduction
#pragma unroll
    for (int mt = 0; mt < 2; ++mt) {
        int r0 = warpM * 32 + mt * 16 + gid;
        int dst0 = sIdx[r0 * 3 + 2];
        int dst1 = sIdx[(r0 + 8) * 3 + 2];
        float* p0 = g_seg + (long long)dst0 * 128;
        float* p1 = g_seg + (long long)dst1 * 128;
#pragma unroll
        for (int nt = 0; nt < 8; ++nt) {
            int c0 = warpN * 64 + nt * 8 + t4 * 2;
            float bv0 = sBias[c0], bv1 = sBias[c0 + 1];
            float x0 = gelu_exact(acc[mt][nt][0] + bv0);
            float x1 = gelu_exact(acc[mt][nt][1] + bv1);
            float x2 = gelu_exact(acc[mt][nt][2] + bv0);
            float x3 = gelu_exact(acc[mt][nt][3] + bv1);
            red2(p0 + c0, x0, x1);
            red2(p1 + c0, x2, x3);
        }
    }
}

// ---------------------------------------------------------------------------
// kernel 2: segment mean + layernorm. One warp per edge.
// ---------------------------------------------------------------------------
__global__ __launch_bounds__(256)
void ln_kernel(const float* __restrict__ gamma,
               const float* __restrict__ beta,
               float* __restrict__ out) {
    const int warp = threadIdx.x >> 5;
    const int lane = threadIdx.x & 31;
    const int e = blockIdx.x * 8 + warp;
    if (e >= E_N) return;

    const float inv = 1.0f / fmaxf(g_cnt[e], 1.0f);
    const long long base = (long long)e * 128;

    float m[4];
    float s = 0.0f;
#pragma unroll
    for (int i = 0; i < 4; ++i) {
        m[i] = g_seg[base + lane + 32 * i] * inv;
        s += m[i];
    }
#pragma unroll
    for (int o = 16; o; o >>= 1) s += __shfl_xor_sync(0xffffffffu, s, o);
    const float mu = s * (1.0f / 128.0f);

    float v = 0.0f;
#pragma unroll
    for (int i = 0; i < 4; ++i) {
        float d = m[i] - mu;
        v += d * d;
    }
#pragma unroll
    for (int o = 16; o; o >>= 1) v += __shfl_xor_sync(0xffffffffu, v, o);
    const float rstd = rsqrtf(v * (1.0f / 128.0f) + 1e-5f);

#pragma unroll
    for (int i = 0; i < 4; ++i) {
        int c = lane + 32 * i;
        out[base + c] = (m[i] - mu) * rstd * gamma[c] + beta[c];
    }
}

// ---------------------------------------------------------------------------
extern "C" void kernel_launch(void* const* d_in, const int* in_sizes, int n_in,
                              void* d_out, int out_size) {
    const float* f_edge = nullptr;
    const float* W      = nullptr;
    const int*   tri    = nullptr;
    const float* vec128[3] = {nullptr, nullptr, nullptr};
    int nv = 0;
    for (int i = 0; i < n_in; ++i) {
        long long sz = in_sizes[i];
        if (sz == (long long)E_N * 128)  f_edge = (const float*)d_in[i];
        else if (sz == 3LL * 128 * 128)  W      = (const float*)d_in[i];
        else if (sz == 3LL * T_N)        tri    = (const int*)d_in[i];
        else if (sz == 128 && nv < 3)    vec128[nv++] = (const float*)d_in[i];
    }
    const float* b     = vec128[0];
    const float* gamma = vec128[1];
    const float* beta  = vec128[2];
    float* out = (float*)d_out;

    cudaFuncSetAttribute(tri_gemm_kernel,
                         cudaFuncAttributeMaxDynamicSharedMemorySize, DYN_SMEM);

    init_kernel<<<12500, 256>>>(f_edge, W);
    tri_gemm_kernel<<<T_N / 128, 256, DYN_SMEM>>>(b, tri);
    ln_kernel<<<E_N / 8, 256>>>(gamma, beta, out);
}

// round 15
// speedup vs baseline: 1.6505x; 1.1891x over previous
#include <cuda_runtime.h>
#include <cuda_fp16.h>
#include <cstdint>

#define E_N 100000
#define T_N 400000

// Scratch (device globals — no runtime alloc).
__device__ float    g_seg[(long long)E_N * 128];
__device__ float    g_cnt[E_N];
__device__ uint32_t g_fh[(long long)E_N * 64];    // f_edge fp16, [e][k] packed half2
__device__ uint32_t g_Wh[128 * 192];              // W fp16 TRANSPOSED: [n][k] half2

// ---------------------------------------------------------------------------
// helpers
// ---------------------------------------------------------------------------
__device__ __forceinline__ void mma16(float c[4], const uint32_t a[4],
                                      uint32_t b0, uint32_t b1) {
    asm volatile(
        "mma.sync.aligned.m16n8k16.row.col.f32.f16.f16.f32 "
        "{%0,%1,%2,%3}, {%4,%5,%6,%7}, {%8,%9}, {%0,%1,%2,%3};\n"
        : "+f"(c[0]), "+f"(c[1]), "+f"(c[2]), "+f"(c[3])
        : "r"(a[0]), "r"(a[1]), "r"(a[2]), "r"(a[3]), "r"(b0), "r"(b1));
}

__device__ __forceinline__ void ldm4(uint32_t r[4], uint32_t addr) {
    asm volatile(
        "ldmatrix.sync.aligned.m8n8.x4.shared.b16 {%0,%1,%2,%3}, [%4];"
        : "=r"(r[0]), "=r"(r[1]), "=r"(r[2]), "=r"(r[3]) : "r"(addr));
}

__device__ __forceinline__ void ldm2(uint32_t& r0, uint32_t& r1, uint32_t addr) {
    asm volatile(
        "ldmatrix.sync.aligned.m8n8.x2.shared.b16 {%0,%1}, [%2];"
        : "=r"(r0), "=r"(r1) : "r"(addr));
}

__device__ __forceinline__ void red2(float* p, float x, float y) {
    asm volatile("red.global.add.v2.f32 [%0], {%1,%2};"
                 :: "l"(p), "f"(x), "f"(y) : "memory");
}

__device__ __forceinline__ float gelu_exact(float x) {
    return 0.5f * x * (1.0f + erff(x * 0.70710678118654752f));
}

__device__ __forceinline__ void cpa16(uint32_t dst_smem, const void* src) {
    asm volatile("cp.async.cg.shared.global [%0], [%1], 16;"
                 :: "r"(dst_smem), "l"(src));
}

__device__ __forceinline__ uint32_t pack2h(float lo, float hi) {
    __half2 h = __floats2half2_rn(lo, hi);
    return *reinterpret_cast<uint32_t*>(&h);
}

// ---------------------------------------------------------------------------
// kernel 0: init — fp16-convert f_edge, fp16-transpose W, zero g_seg / g_cnt
// ---------------------------------------------------------------------------
__global__ void init_kernel(const float* __restrict__ fe,
                            const float* __restrict__ W) {
    int i = blockIdx.x * 256 + threadIdx.x;          // 0 .. 3.2M-1
    float4 v = ((const float4*)fe)[i];
    g_fh[2 * i]     = pack2h(v.x, v.y);
    g_fh[2 * i + 1] = pack2h(v.z, v.w);
    ((float4*)g_seg)[i] = make_float4(0.f, 0.f, 0.f, 0.f);
    if (i < 24576) {                                  // 128 n x 192 k-pairs
        int n = i / 192, kk = i % 192;
        g_Wh[n * 192 + kk] = pack2h(W[(2 * kk) * 128 + n],
                                    W[(2 * kk + 1) * 128 + n]);
    }
    if (i < E_N) g_cnt[i] = 0.0f;
}

// ---------------------------------------------------------------------------
// kernel 1: gather + fp16 GEMM (3-stage cp.async, ldmatrix fragments)
//           + exact GELU + fire-and-forget REDG scatter
//   BM=128, BN=128, BK=32, 12 chunks, 3 smem stages, 1 barrier/chunk.
//   A smem: [m][k] fp16, row stride 20 u32 (80 B);  B smem: [n][k], same.
// ---------------------------------------------------------------------------
#define NSTAGE   3
#define RS       20                          // u32 row stride (A and B)
#define STAGE_U32 (128 * RS * 2)             // A + B = 5120 u32
#define DYN_SMEM  (NSTAGE * STAGE_U32 * 4)   // 61440 B

__global__ __launch_bounds__(256, 2)
void tri_gemm_kernel(const float* __restrict__ bias,
                     const int* __restrict__ tri) {
    extern __shared__ uint32_t dyn[];
    __shared__ int   sIdx[384];              // [128][3]
    __shared__ float sBias[128];

    const int tid = threadIdx.x;
    const int t0  = blockIdx.x * 128;        // T = 3125 * 128

    for (int i = tid; i < 384; i += 256) sIdx[i] = tri[(long long)t0 * 3 + i];
    if (tid < 128) sBias[tid] = bias[tid];
    __syncthreads();

    if (tid < 128) atomicAdd(&g_cnt[sIdx[tid * 3 + 2]], 1.0f);

    const int lane  = tid & 31;
    const int warp  = tid >> 5;
    const int warpM = warp & 3;
    const int warpN = warp >> 2;
    const int gid   = lane >> 2;
    const int t4    = lane & 3;

    const uint32_t dynb = (uint32_t)__cvta_generic_to_shared(dyn);

    // ldmatrix per-lane address components (byte offsets within a stage)
    //  A x4: lanes0-7 -> (row, k0); 8-15 -> (row+8, k0); 16-23 -> (row, k0+16B);
    //        24-31 -> (row+8, k0+16B)   [a0..a3 fragment order]
    const uint32_t aRowOff = (uint32_t)(warpM * 32 + ((lane >> 3) & 1) * 8
                                        + (lane & 7)) * (RS * 4)
                             + (uint32_t)(lane >> 4) * 16;
    //  B x2: lanes0-7 -> (row, +0); 8-15 -> (row, +16B)
    const uint32_t bRowOff = (uint32_t)(128 * RS * 4)
                             + (uint32_t)(warpN * 64 + (lane & 7)) * (RS * 4)
                             + (uint32_t)((lane >> 3) & 1) * 16;

    float acc[2][8][4];
#pragma unroll
    for (int a = 0; a < 2; ++a)
#pragma unroll
        for (int b = 0; b < 8; ++b)
#pragma unroll
            for (int c = 0; c < 4; ++c) acc[a][b][c] = 0.0f;

    auto load_chunk = [&](int ch) {
        const int st  = ch % NSTAGE;
        const int j   = ch >> 2;             // edge slot 0..2 (4 chunks each)
        const int ko  = (ch & 3) * 16;       // u32 offset within edge row
        const uint32_t aB = dynb + (st * STAGE_U32) * 4;
        const uint32_t bB = aB + 128 * RS * 4;
#pragma unroll
        for (int s = 0; s < 2; ++s) {
            int fid = tid + s * 256;
            int r = fid >> 2, part = fid & 3;
            cpa16(aB + (r * RS + part * 4) * 4,
                  g_fh + (long long)sIdx[r * 3 + j] * 64 + ko + part * 4);
            cpa16(bB + (r * RS + part * 4) * 4,
                  g_Wh + r * 192 + ch * 16 + part * 4);
        }
        asm volatile("cp.async.commit_group;" ::: "memory");
    };

    load_chunk(0);
    load_chunk(1);

    for (int ch = 0; ch < 12; ++ch) {
        asm volatile("cp.async.wait_group 1;" ::: "memory");
        __syncthreads();
        if (ch + 2 < 12) load_chunk(ch + 2);

        const uint32_t sb = dynb + ((ch % NSTAGE) * STAGE_U32) * 4;
#pragma unroll
        for (int kk = 0; kk < 2; ++kk) {
            const uint32_t k0b = kk * 32;    // 8 u32 = 32 B per k16 block
            uint32_t a0[4], a1[4];
            ldm4(a0, sb + aRowOff + k0b);
            ldm4(a1, sb + aRowOff + k0b + 16 * RS * 4);
#pragma unroll
            for (int nt = 0; nt < 8; ++nt) {
                uint32_t b0, b1;
                ldm2(b0, b1, sb + bRowOff + nt * 8 * RS * 4 + k0b);
                mma16(acc[0][nt], a0, b0, b1);
                mma16(acc[1][nt], a1, b0, b1);
            }
        }
    }

    // Epilogue: bias + exact GELU + fire-and-forget vectorized reduction
#pragma unroll
    for (int mt = 0; mt < 2; ++mt) {
        int r0 = warpM * 32 + mt * 16 + gid;
        int dst0 = sIdx[r0 * 3 + 2];
        int dst1 = sIdx[(r0 + 8) * 3 + 2];
        float* p0 = g_seg + (long long)dst0 * 128;
        float* p1 = g_seg + (long long)dst1 * 128;
#pragma unroll
        for (int nt = 0; nt < 8; ++nt) {
            int c0 = warpN * 64 + nt * 8 + t4 * 2;
            float bv0 = sBias[c0], bv1 = sBias[c0 + 1];
            float x0 = gelu_exact(acc[mt][nt][0] + bv0);
            float x1 = gelu_exact(acc[mt][nt][1] + bv1);
            float x2 = gelu_exact(acc[mt][nt][2] + bv0);
            float x3 = gelu_exact(acc[mt][nt][3] + bv1);
            red2(p0 + c0, x0, x1);
            red2(p1 + c0, x2, x3);
        }
    }
}

// ---------------------------------------------------------------------------
// kernel 2: segment mean + layernorm. One warp per edge.
// ---------------------------------------------------------------------------
__global__ __launch_bounds__(256)
void ln_kernel(const float* __restrict__ gamma,
               const float* __restrict__ beta,
               float* __restrict__ out) {
    const int warp = threadIdx.x >> 5;
    const int lane = threadIdx.x & 31;
    const int e = blockIdx.x * 8 + warp;
    if (e >= E_N) return;

    const float inv = 1.0f / fmaxf(g_cnt[e], 1.0f);
    const long long base = (long long)e * 128;

    float m[4];
    float s = 0.0f;
#pragma unroll
    for (int i = 0; i < 4; ++i) {
        m[i] = g_seg[base + lane + 32 * i] * inv;
        s += m[i];
    }
#pragma unroll
    for (int o = 16; o; o >>= 1) s += __shfl_xor_sync(0xffffffffu, s, o);
    const float mu = s * (1.0f / 128.0f);

    float v = 0.0f;
#pragma unroll
    for (int i = 0; i < 4; ++i) {
        float d = m[i] - mu;
        v += d * d;
    }
#pragma unroll
    for (int o = 16; o; o >>= 1) v += __shfl_xor_sync(0xffffffffu, v, o);
    const float rstd = rsqrtf(v * (1.0f / 128.0f) + 1e-5f);

#pragma unroll
    for (int i = 0; i < 4; ++i) {
        int c = lane + 32 * i;
        out[base + c] = (m[i] - mu) * rstd * gamma[c] + beta[c];
    }
}

// ---------------------------------------------------------------------------
extern "C" void kernel_launch(void* const* d_in, const int* in_sizes, int n_in,
                              void* d_out, int out_size) {
    const float* f_edge = nullptr;
    const float* W      = nullptr;
    const int*   tri    = nullptr;
    const float* vec128[3] = {nullptr, nullptr, nullptr};
    int nv = 0;
    for (int i = 0; i < n_in; ++i) {
        long long sz = in_sizes[i];
        if (sz == (long long)E_N * 128)  f_edge = (const float*)d_in[i];
        else if (sz == 3LL * 128 * 128)  W      = (const float*)d_in[i];
        else if (sz == 3LL * T_N)        tri    = (const int*)d_in[i];
        else if (sz == 128 && nv < 3)    vec128[nv++] = (const float*)d_in[i];
    }
    const float* b     = vec128[0];
    const float* gamma = vec128[1];
    const float* beta  = vec128[2];
    float* out = (float*)d_out;

    cudaFuncSetAttribute(tri_gemm_kernel,
                         cudaFuncAttributeMaxDynamicSharedMemorySize, DYN_SMEM);

    init_kernel<<<12500, 256>>>(f_edge, W);
    tri_gemm_kernel<<<T_N / 128, 256, DYN_SMEM>>>(b, tri);
    ln_kernel<<<E_N / 8, 256>>>(gamma, beta, out);
}